// round 1
// baseline (speedup 1.0000x reference)
#include <cuda_runtime.h>
#include <cuda_fp16.h>
#include <math.h>
#include <stdint.h>

#define NP 8192
#define MP 8192
#define DIMS 32
#define EPSV 10.0f
#define THRESH2 (1e-5f * 1e-5f)
#define MAX_ITER 50
#define SCALE_F 65536.0f
#define INV_SCALE_F (1.0f / 65536.0f)
#define LOG_SCALE_F 11.090354888959125f /* ln(65536) */

// Scratch: K (scaled fp16) stored both row-major and transposed. 256MB total.
__device__ __half g_K1[(size_t)NP * MP];
__device__ __half g_K2[(size_t)NP * MP];
__device__ float g_a[NP];
__device__ float g_b[MP];
__device__ float g_bnew[MP];
__device__ int   g_done;
__device__ float g_part[65536];

// ---------------------------------------------------------------------------
__global__ void sink_init()
{
    int i = blockIdx.x * 256 + threadIdx.x;
    if (i < MP) g_b[i] = 1.0f;
    if (i == 0) g_done = 0;
}

// ---------------------------------------------------------------------------
// Build K' = min(65504, 2^16 * exp(-max(C,0)/EPS)) in fp16, plus its transpose.
// 64x64 tile per block, 256 threads, 4x4 micro-tile per thread.
__global__ __launch_bounds__(256) void build_K(const float* __restrict__ x,
                                               const float* __restrict__ y)
{
    __shared__ float sx[64][DIMS + 1];
    __shared__ float sy[64][DIMS + 1];
    __shared__ float sx2[64];
    __shared__ float sy2[64];
    __shared__ __half stile[64][65];

    const int tid = threadIdx.x;
    const int I0 = blockIdx.y * 64;
    const int J0 = blockIdx.x * 64;

    for (int idx = tid; idx < 64 * DIMS; idx += 256) {
        int r = idx >> 5, k = idx & 31;
        sx[r][k] = x[(I0 + r) * DIMS + k];
        sy[r][k] = y[(J0 + r) * DIMS + k];
    }
    __syncthreads();
    if (tid < 64) {
        float s = 0.f;
        #pragma unroll
        for (int k = 0; k < DIMS; k++) { float v = sx[tid][k]; s = fmaf(v, v, s); }
        sx2[tid] = s;
    } else if (tid < 128) {
        int r = tid - 64;
        float s = 0.f;
        #pragma unroll
        for (int k = 0; k < DIMS; k++) { float v = sy[r][k]; s = fmaf(v, v, s); }
        sy2[r] = s;
    }
    __syncthreads();

    const int ty = tid >> 4, tx = tid & 15;
    const int r0 = ty * 4, c0 = tx * 4;
    float acc[4][4];
    #pragma unroll
    for (int i = 0; i < 4; i++)
        #pragma unroll
        for (int j = 0; j < 4; j++) acc[i][j] = 0.f;

    #pragma unroll
    for (int k = 0; k < DIMS; k++) {
        float a0 = sx[r0 + 0][k], a1 = sx[r0 + 1][k];
        float a2 = sx[r0 + 2][k], a3 = sx[r0 + 3][k];
        float b0 = sy[c0 + 0][k], b1 = sy[c0 + 1][k];
        float b2 = sy[c0 + 2][k], b3 = sy[c0 + 3][k];
        acc[0][0] = fmaf(a0, b0, acc[0][0]); acc[0][1] = fmaf(a0, b1, acc[0][1]);
        acc[0][2] = fmaf(a0, b2, acc[0][2]); acc[0][3] = fmaf(a0, b3, acc[0][3]);
        acc[1][0] = fmaf(a1, b0, acc[1][0]); acc[1][1] = fmaf(a1, b1, acc[1][1]);
        acc[1][2] = fmaf(a1, b2, acc[1][2]); acc[1][3] = fmaf(a1, b3, acc[1][3]);
        acc[2][0] = fmaf(a2, b0, acc[2][0]); acc[2][1] = fmaf(a2, b1, acc[2][1]);
        acc[2][2] = fmaf(a2, b2, acc[2][2]); acc[2][3] = fmaf(a2, b3, acc[2][3]);
        acc[3][0] = fmaf(a3, b0, acc[3][0]); acc[3][1] = fmaf(a3, b1, acc[3][1]);
        acc[3][2] = fmaf(a3, b2, acc[3][2]); acc[3][3] = fmaf(a3, b3, acc[3][3]);
    }

    #pragma unroll
    for (int i = 0; i < 4; i++) {
        #pragma unroll
        for (int j = 0; j < 4; j++) {
            float C = sx2[r0 + i] + sy2[c0 + j] - 2.f * acc[i][j];
            C = fmaxf(C, 0.f);
            // exp(-C/10) * 2^16 == exp2(16 - C*log2(e)/10)
            float kv = exp2f(fmaf(C, -0.14426950408889634f, 16.0f));
            kv = fminf(kv, 65504.f);
            stile[r0 + i][c0 + j] = __float2half_rn(kv);
        }
    }
    __syncthreads();

    for (int idx = tid; idx < 4096; idx += 256) {
        int r = idx >> 6, c = idx & 63;
        g_K1[(size_t)(I0 + r) * MP + (J0 + c)] = stile[r][c];
        g_K2[(size_t)(J0 + r) * NP + (I0 + c)] = stile[c][r];
    }
}

// ---------------------------------------------------------------------------
// vout[row] = mul[row] * SCALE / sum_j K[row][j] * vin[j]
// 256 threads = 8 warps, 1 row per warp, b staged in shared with 8x1024
// swizzle so LDS reads are conflict-free against the per-lane uint4 K loads.
__global__ __launch_bounds__(256) void sink_matvec(const __half* __restrict__ K,
                                                   const float* __restrict__ vin,
                                                   const float* __restrict__ mul,
                                                   float* __restrict__ vout)
{
    if (g_done) return;
    __shared__ float sbw[8][1024];
    for (int i = threadIdx.x; i < MP; i += 256)
        sbw[i & 7][i >> 3] = vin[i];
    __syncthreads();

    const int warp = threadIdx.x >> 5;
    const int lane = threadIdx.x & 31;
    const int row = blockIdx.x * 8 + warp;
    const uint4* __restrict__ kr = (const uint4*)(K + (size_t)row * MP);

    float acc = 0.f;
    #pragma unroll 4
    for (int it = 0; it < 32; ++it) {
        const int j8 = it * 32 + lane;
        uint4 v = kr[j8];
        __half2 h0 = *reinterpret_cast<__half2*>(&v.x);
        __half2 h1 = *reinterpret_cast<__half2*>(&v.y);
        __half2 h2 = *reinterpret_cast<__half2*>(&v.z);
        __half2 h3 = *reinterpret_cast<__half2*>(&v.w);
        float2 f0 = __half22float2(h0);
        float2 f1 = __half22float2(h1);
        float2 f2 = __half22float2(h2);
        float2 f3 = __half22float2(h3);
        acc = fmaf(f0.x, sbw[0][j8], acc);
        acc = fmaf(f0.y, sbw[1][j8], acc);
        acc = fmaf(f1.x, sbw[2][j8], acc);
        acc = fmaf(f1.y, sbw[3][j8], acc);
        acc = fmaf(f2.x, sbw[4][j8], acc);
        acc = fmaf(f2.y, sbw[5][j8], acc);
        acc = fmaf(f3.x, sbw[6][j8], acc);
        acc = fmaf(f3.y, sbw[7][j8], acc);
    }
    #pragma unroll
    for (int o = 16; o; o >>= 1) acc += __shfl_xor_sync(0xffffffffu, acc, o);
    if (lane == 0) vout[row] = mul[row] * SCALE_F / acc;
}

// ---------------------------------------------------------------------------
// err = ||bnew - b||, copy bnew -> b, set done if converged. Deterministic.
__global__ __launch_bounds__(256) void sink_update()
{
    if (g_done) return;
    __shared__ float sd[256];
    float s = 0.f;
    for (int i = threadIdx.x; i < MP; i += 256) {
        float d = g_bnew[i] - g_b[i];
        s = fmaf(d, d, s);
        g_b[i] = g_bnew[i];
    }
    sd[threadIdx.x] = s;
    __syncthreads();
    for (int o = 128; o; o >>= 1) {
        if (threadIdx.x < o) sd[threadIdx.x] += sd[threadIdx.x + o];
        __syncthreads();
    }
    if (threadIdx.x == 0 && sd[0] < THRESH2) g_done = 1;
}

// ---------------------------------------------------------------------------
// T = a * (K'/S) * b; cost term = T * C with C = EPS*(ln S - ln K').
// 1024 elements per block (one row segment), per-block partial in fixed slot.
__global__ __launch_bounds__(256) void finalize_T(float* __restrict__ Tout,
                                                  int write_T)
{
    const size_t e0 = ((size_t)blockIdx.x * 1024) + (size_t)threadIdx.x * 4;
    const int i = (int)(e0 >> 13);
    const int j = (int)(e0 & 8191);
    const float ai = g_a[i] * INV_SCALE_F;

    uint2 kv2 = *reinterpret_cast<const uint2*>(g_K1 + e0);
    __half2 h0 = *reinterpret_cast<__half2*>(&kv2.x);
    __half2 h1 = *reinterpret_cast<__half2*>(&kv2.y);
    float2 f0 = __half22float2(h0);
    float2 f1 = __half22float2(h1);
    const float4 bv = *reinterpret_cast<const float4*>(g_b + j);

    float t0 = ai * f0.x * bv.x;
    float t1 = ai * f0.y * bv.y;
    float t2 = ai * f1.x * bv.z;
    float t3 = ai * f1.y * bv.w;

    float cs = 0.f;
    if (f0.x > 0.f) cs = fmaf(t0, EPSV * (LOG_SCALE_F - __logf(f0.x)), cs);
    if (f0.y > 0.f) cs = fmaf(t1, EPSV * (LOG_SCALE_F - __logf(f0.y)), cs);
    if (f1.x > 0.f) cs = fmaf(t2, EPSV * (LOG_SCALE_F - __logf(f1.x)), cs);
    if (f1.y > 0.f) cs = fmaf(t3, EPSV * (LOG_SCALE_F - __logf(f1.y)), cs);

    if (write_T) {
        if ((((uintptr_t)Tout) & 15) == 0) {
            *reinterpret_cast<float4*>(Tout + e0) = make_float4(t0, t1, t2, t3);
        } else {
            Tout[e0 + 0] = t0;
            Tout[e0 + 1] = t1;
            Tout[e0 + 2] = t2;
            Tout[e0 + 3] = t3;
        }
    }

    __shared__ float sd[256];
    sd[threadIdx.x] = cs;
    __syncthreads();
    for (int o = 128; o; o >>= 1) {
        if (threadIdx.x < o) sd[threadIdx.x] += sd[threadIdx.x + o];
        __syncthreads();
    }
    if (threadIdx.x == 0) g_part[blockIdx.x] = sd[0];
}

__global__ __launch_bounds__(256) void reduce_cost(float* __restrict__ cost_out)
{
    __shared__ double sd[256];
    double s = 0.0;
    for (int i = threadIdx.x; i < 65536; i += 256) s += (double)g_part[i];
    sd[threadIdx.x] = s;
    __syncthreads();
    for (int o = 128; o; o >>= 1) {
        if (threadIdx.x < o) sd[threadIdx.x] += sd[threadIdx.x + o];
        __syncthreads();
    }
    if (threadIdx.x == 0) cost_out[0] = (float)sd[0];
}

// ---------------------------------------------------------------------------
extern "C" void kernel_launch(void* const* d_in, const int* in_sizes, int n_in,
                              void* d_out, int out_size)
{
    const float* x = (const float*)d_in[0];
    const float* y = (const float*)d_in[1];
    const float* p = (const float*)d_in[2];
    const float* q = (const float*)d_in[3];
    float* out = (float*)d_out;

    void *k1p, *k2p, *ap, *bp, *bnp;
    cudaGetSymbolAddress(&k1p, g_K1);
    cudaGetSymbolAddress(&k2p, g_K2);
    cudaGetSymbolAddress(&ap, g_a);
    cudaGetSymbolAddress(&bp, g_b);
    cudaGetSymbolAddress(&bnp, g_bnew);

    sink_init<<<32, 256>>>();
    dim3 bgrid(MP / 64, NP / 64);
    build_K<<<bgrid, 256>>>(x, y);

    for (int it = 0; it < MAX_ITER; ++it) {
        sink_matvec<<<NP / 8, 256>>>((const __half*)k1p, (const float*)bp, p,
                                     (float*)ap);
        sink_matvec<<<MP / 8, 256>>>((const __half*)k2p, (const float*)ap, q,
                                     (float*)bnp);
        sink_update<<<1, 256>>>();
    }

    const long long total = (long long)NP * MP;
    if ((long long)out_size == total + 1) {
        // (w_cost, T) flattened: cost at [0], T row-major after.
        finalize_T<<<65536, 256>>>(out + 1, 1);
        reduce_cost<<<1, 256>>>(out);
    } else if ((long long)out_size == total) {
        finalize_T<<<65536, 256>>>(out, 1);
    } else if ((long long)out_size > total) {
        finalize_T<<<65536, 256>>>(out + (out_size - total), 1);
        reduce_cost<<<1, 256>>>(out);
    } else {
        finalize_T<<<65536, 256>>>(nullptr, 0);
        reduce_cost<<<1, 256>>>(out);
    }
}

// round 2
// speedup vs baseline: 1.1865x; 1.1865x over previous
#include <cuda_runtime.h>
#include <cuda_fp16.h>
#include <math.h>
#include <stdint.h>

#define NP 8192
#define MP 8192
#define DIMS 32
#define EPSV 10.0f
#define THRESH2 (1e-5f * 1e-5f)
#define MAX_ITER 50
#define SCALE_F 65536.0f
#define INV_SCALE_F (1.0f / 65536.0f)
#define LOG_SCALE_F 11.090354888959125f /* ln(65536) */
#define CS 4
#define CHUNK (MP / CS) /* 2048 */
#define RPB 32          /* rows per block */

// Scratch: K (scaled fp16) stored both row-major and transposed. 256MB total.
__device__ __half g_K1[(size_t)NP * MP];
__device__ __half g_K2[(size_t)NP * MP];
__device__ float g_a[NP];
__device__ float g_b[MP];
__device__ float g_pa[CS * NP]; // partial sums of K @ b   (layout [cs][row])
__device__ float g_pb[CS * MP]; // partial sums of K^T @ a (layout [cs][row])
__device__ int   g_done;
__device__ float g_part[16384];

// ---------------------------------------------------------------------------
__global__ void sink_init()
{
    int i = blockIdx.x * 256 + threadIdx.x;
    if (i < MP) g_b[i] = 1.0f;
    if (i == 0) g_done = 0;
}

// ---------------------------------------------------------------------------
// Build K' = min(65504, 2^16 * exp(-max(C,0)/EPS)) in fp16, plus its transpose.
__global__ __launch_bounds__(256) void build_K(const float* __restrict__ x,
                                               const float* __restrict__ y)
{
    __shared__ float sx[64][DIMS + 1];
    __shared__ float sy[64][DIMS + 1];
    __shared__ float sx2[64];
    __shared__ float sy2[64];
    __shared__ __half stile[64][65];

    const int tid = threadIdx.x;
    const int I0 = blockIdx.y * 64;
    const int J0 = blockIdx.x * 64;

    for (int idx = tid; idx < 64 * DIMS; idx += 256) {
        int r = idx >> 5, k = idx & 31;
        sx[r][k] = x[(I0 + r) * DIMS + k];
        sy[r][k] = y[(J0 + r) * DIMS + k];
    }
    __syncthreads();
    if (tid < 64) {
        float s = 0.f;
        #pragma unroll
        for (int k = 0; k < DIMS; k++) { float v = sx[tid][k]; s = fmaf(v, v, s); }
        sx2[tid] = s;
    } else if (tid < 128) {
        int r = tid - 64;
        float s = 0.f;
        #pragma unroll
        for (int k = 0; k < DIMS; k++) { float v = sy[r][k]; s = fmaf(v, v, s); }
        sy2[r] = s;
    }
    __syncthreads();

    const int ty = tid >> 4, tx = tid & 15;
    const int r0 = ty * 4, c0 = tx * 4;
    float acc[4][4];
    #pragma unroll
    for (int i = 0; i < 4; i++)
        #pragma unroll
        for (int j = 0; j < 4; j++) acc[i][j] = 0.f;

    #pragma unroll
    for (int k = 0; k < DIMS; k++) {
        float a0 = sx[r0 + 0][k], a1 = sx[r0 + 1][k];
        float a2 = sx[r0 + 2][k], a3 = sx[r0 + 3][k];
        float b0 = sy[c0 + 0][k], b1 = sy[c0 + 1][k];
        float b2 = sy[c0 + 2][k], b3 = sy[c0 + 3][k];
        acc[0][0] = fmaf(a0, b0, acc[0][0]); acc[0][1] = fmaf(a0, b1, acc[0][1]);
        acc[0][2] = fmaf(a0, b2, acc[0][2]); acc[0][3] = fmaf(a0, b3, acc[0][3]);
        acc[1][0] = fmaf(a1, b0, acc[1][0]); acc[1][1] = fmaf(a1, b1, acc[1][1]);
        acc[1][2] = fmaf(a1, b2, acc[1][2]); acc[1][3] = fmaf(a1, b3, acc[1][3]);
        acc[2][0] = fmaf(a2, b0, acc[2][0]); acc[2][1] = fmaf(a2, b1, acc[2][1]);
        acc[2][2] = fmaf(a2, b2, acc[2][2]); acc[2][3] = fmaf(a2, b3, acc[2][3]);
        acc[3][0] = fmaf(a3, b0, acc[3][0]); acc[3][1] = fmaf(a3, b1, acc[3][1]);
        acc[3][2] = fmaf(a3, b2, acc[3][2]); acc[3][3] = fmaf(a3, b3, acc[3][3]);
    }

    #pragma unroll
    for (int i = 0; i < 4; i++) {
        #pragma unroll
        for (int j = 0; j < 4; j++) {
            float C = sx2[r0 + i] + sy2[c0 + j] - 2.f * acc[i][j];
            C = fmaxf(C, 0.f);
            float kv = exp2f(fmaf(C, -0.14426950408889634f, 16.0f));
            kv = fminf(kv, 65504.f);
            stile[r0 + i][c0 + j] = __float2half_rn(kv);
        }
    }
    __syncthreads();

    for (int idx = tid; idx < 4096; idx += 256) {
        int r = idx >> 6, c = idx & 63;
        g_K1[(size_t)(I0 + r) * MP + (J0 + c)] = stile[r][c];
        g_K2[(size_t)(J0 + r) * NP + (I0 + c)] = stile[c][r];
    }
}

// ---------------------------------------------------------------------------
// Column-split GEMV partial: block (rowblock, cs) computes, for 32 rows, the
// dot of K[row][cs*2048 .. +2048) with the staged vector chunk, writing raw
// partial sums to part_out[cs*8192 + row]. The input vector is either read
// directly (vin_full) or reconstructed on the fly from the previous matvec's
// partials: v[i] = mul_in[i]*S / sum_c part_in[c*8192+i].
#define ROWFMA(acc, v)                                                      \
    {                                                                       \
        float2 f0 = __half22float2(*reinterpret_cast<__half2*>(&(v).x));    \
        float2 f1 = __half22float2(*reinterpret_cast<__half2*>(&(v).y));    \
        float2 f2 = __half22float2(*reinterpret_cast<__half2*>(&(v).z));    \
        float2 f3 = __half22float2(*reinterpret_cast<__half2*>(&(v).w));    \
        acc = fmaf(f0.x, b0, acc); acc = fmaf(f0.y, b1, acc);               \
        acc = fmaf(f1.x, b2, acc); acc = fmaf(f1.y, b3, acc);               \
        acc = fmaf(f2.x, b4, acc); acc = fmaf(f2.y, b5, acc);               \
        acc = fmaf(f3.x, b6, acc); acc = fmaf(f3.y, b7, acc);               \
    }

__global__ __launch_bounds__(256) void sink_matvec(
    const __half* __restrict__ K, const float* __restrict__ vin_full,
    const float* __restrict__ part_in, const float* __restrict__ mul_in,
    float* __restrict__ part_out)
{
    if (g_done) return;
    __shared__ float sbw[8][CHUNK / 8 + 1]; // [8][257] pad: conflict-free r/w

    const int cs = blockIdx.x & (CS - 1);
    const int rowblock = blockIdx.x >> 2;
    const int i0 = cs * CHUNK;

    for (int idx = threadIdx.x; idx < CHUNK; idx += 256) {
        int i = i0 + idx;
        float v;
        if (part_in) {
            float s = part_in[i] + part_in[NP + i] + part_in[2 * NP + i] +
                      part_in[3 * NP + i];
            v = __fdividef(mul_in[i] * SCALE_F, s);
        } else {
            v = vin_full[i];
        }
        sbw[idx & 7][idx >> 3] = v;
    }
    __syncthreads();

    const int warp = threadIdx.x >> 5;
    const int lane = threadIdx.x & 31;
    const int rbase = rowblock * RPB + warp * 4;
    const uint4* __restrict__ k0 = (const uint4*)(K + (size_t)(rbase + 0) * MP + i0);
    const uint4* __restrict__ k1 = (const uint4*)(K + (size_t)(rbase + 1) * MP + i0);
    const uint4* __restrict__ k2 = (const uint4*)(K + (size_t)(rbase + 2) * MP + i0);
    const uint4* __restrict__ k3 = (const uint4*)(K + (size_t)(rbase + 3) * MP + i0);

    float a0 = 0.f, a1 = 0.f, a2 = 0.f, a3 = 0.f;
    #pragma unroll 2
    for (int it = 0; it < CHUNK / 256; ++it) { // 8 iterations
        const int idx = it * 32 + lane;
        uint4 v0 = k0[idx];
        uint4 v1 = k1[idx];
        uint4 v2 = k2[idx];
        uint4 v3 = k3[idx];
        float b0 = sbw[0][idx], b1 = sbw[1][idx];
        float b2 = sbw[2][idx], b3 = sbw[3][idx];
        float b4 = sbw[4][idx], b5 = sbw[5][idx];
        float b6 = sbw[6][idx], b7 = sbw[7][idx];
        ROWFMA(a0, v0);
        ROWFMA(a1, v1);
        ROWFMA(a2, v2);
        ROWFMA(a3, v3);
    }
    #pragma unroll
    for (int o = 16; o; o >>= 1) {
        a0 += __shfl_xor_sync(0xffffffffu, a0, o);
        a1 += __shfl_xor_sync(0xffffffffu, a1, o);
        a2 += __shfl_xor_sync(0xffffffffu, a2, o);
        a3 += __shfl_xor_sync(0xffffffffu, a3, o);
    }
    if (lane == 0) {
        float* po = part_out + (size_t)cs * NP + rbase;
        po[0] = a0; po[1] = a1; po[2] = a2; po[3] = a3;
    }
}

// ---------------------------------------------------------------------------
// Combine b-partials -> bnew, err = ||bnew - b||^2, update g_b, set done.
__global__ __launch_bounds__(256) void sink_update(const float* __restrict__ q)
{
    if (g_done) return;
    __shared__ float sd[256];
    const int base = threadIdx.x * 32;
    float errs = 0.f;
    #pragma unroll
    for (int g = 0; g < 8; ++g) {
        int i = base + g * 4;
        float4 p0 = *(const float4*)(g_pb + i);
        float4 p1 = *(const float4*)(g_pb + MP + i);
        float4 p2 = *(const float4*)(g_pb + 2 * MP + i);
        float4 p3 = *(const float4*)(g_pb + 3 * MP + i);
        float4 qv = *(const float4*)(q + i);
        float4 ob = *(const float4*)(g_b + i);
        float n0 = __fdividef(qv.x * SCALE_F, p0.x + p1.x + p2.x + p3.x);
        float n1 = __fdividef(qv.y * SCALE_F, p0.y + p1.y + p2.y + p3.y);
        float n2 = __fdividef(qv.z * SCALE_F, p0.z + p1.z + p2.z + p3.z);
        float n3 = __fdividef(qv.w * SCALE_F, p0.w + p1.w + p2.w + p3.w);
        float d0 = n0 - ob.x, d1 = n1 - ob.y, d2 = n2 - ob.z, d3 = n3 - ob.w;
        errs = fmaf(d0, d0, errs); errs = fmaf(d1, d1, errs);
        errs = fmaf(d2, d2, errs); errs = fmaf(d3, d3, errs);
        *(float4*)(g_b + i) = make_float4(n0, n1, n2, n3);
    }
    sd[threadIdx.x] = errs;
    __syncthreads();
    for (int o = 128; o; o >>= 1) {
        if (threadIdx.x < o) sd[threadIdx.x] += sd[threadIdx.x + o];
        __syncthreads();
    }
    if (threadIdx.x == 0 && sd[0] < THRESH2) g_done = 1;
}

// ---------------------------------------------------------------------------
__global__ void combine_a(const float* __restrict__ p)
{
    int i = blockIdx.x * 256 + threadIdx.x;
    float s = g_pa[i] + g_pa[NP + i] + g_pa[2 * NP + i] + g_pa[3 * NP + i];
    g_a[i] = __fdividef(p[i] * SCALE_F, s);
}

// ---------------------------------------------------------------------------
// T = a * (K'/S) * b; cost term = T * C with C = EPS*(ln S - ln K').
// 16 elements per thread, one row per block (4096 elems/block).
__global__ __launch_bounds__(256) void finalize_T(float* __restrict__ Tout,
                                                  int write_T)
{
    const size_t e0 = ((size_t)blockIdx.x * 4096) + (size_t)threadIdx.x * 16;
    const int i = (int)(e0 >> 13);
    const float ai = g_a[i] * INV_SCALE_F;
    float cs = 0.f;

    #pragma unroll
    for (int g = 0; g < 4; ++g) {
        const size_t e = e0 + g * 4;
        const int j = (int)(e & 8191);
        uint2 kv2 = *reinterpret_cast<const uint2*>(g_K1 + e);
        __half2 h0 = *reinterpret_cast<__half2*>(&kv2.x);
        __half2 h1 = *reinterpret_cast<__half2*>(&kv2.y);
        float2 f0 = __half22float2(h0);
        float2 f1 = __half22float2(h1);
        const float4 bv = *reinterpret_cast<const float4*>(g_b + j);

        float t0 = ai * f0.x * bv.x;
        float t1 = ai * f0.y * bv.y;
        float t2 = ai * f1.x * bv.z;
        float t3 = ai * f1.y * bv.w;

        if (f0.x > 0.f) cs = fmaf(t0, EPSV * (LOG_SCALE_F - __logf(f0.x)), cs);
        if (f0.y > 0.f) cs = fmaf(t1, EPSV * (LOG_SCALE_F - __logf(f0.y)), cs);
        if (f1.x > 0.f) cs = fmaf(t2, EPSV * (LOG_SCALE_F - __logf(f1.x)), cs);
        if (f1.y > 0.f) cs = fmaf(t3, EPSV * (LOG_SCALE_F - __logf(f1.y)), cs);

        if (write_T) {
            if ((((uintptr_t)Tout) & 15) == 0) {
                *reinterpret_cast<float4*>(Tout + e) = make_float4(t0, t1, t2, t3);
            } else {
                Tout[e + 0] = t0;
                Tout[e + 1] = t1;
                Tout[e + 2] = t2;
                Tout[e + 3] = t3;
            }
        }
    }

    __shared__ float sd[256];
    sd[threadIdx.x] = cs;
    __syncthreads();
    for (int o = 128; o; o >>= 1) {
        if (threadIdx.x < o) sd[threadIdx.x] += sd[threadIdx.x + o];
        __syncthreads();
    }
    if (threadIdx.x == 0) g_part[blockIdx.x] = sd[0];
}

__global__ __launch_bounds__(256) void reduce_cost(float* __restrict__ cost_out)
{
    __shared__ double sd[256];
    double s = 0.0;
    for (int i = threadIdx.x; i < 16384; i += 256) s += (double)g_part[i];
    sd[threadIdx.x] = s;
    __syncthreads();
    for (int o = 128; o; o >>= 1) {
        if (threadIdx.x < o) sd[threadIdx.x] += sd[threadIdx.x + o];
        __syncthreads();
    }
    if (threadIdx.x == 0) cost_out[0] = (float)sd[0];
}

// ---------------------------------------------------------------------------
extern "C" void kernel_launch(void* const* d_in, const int* in_sizes, int n_in,
                              void* d_out, int out_size)
{
    const float* x = (const float*)d_in[0];
    const float* y = (const float*)d_in[1];
    const float* p = (const float*)d_in[2];
    const float* q = (const float*)d_in[3];
    float* out = (float*)d_out;

    void *k1p, *k2p, *bp, *pap, *pbp;
    cudaGetSymbolAddress(&k1p, g_K1);
    cudaGetSymbolAddress(&k2p, g_K2);
    cudaGetSymbolAddress(&bp, g_b);
    cudaGetSymbolAddress(&pap, g_pa);
    cudaGetSymbolAddress(&pbp, g_pb);

    sink_init<<<32, 256>>>();
    dim3 bgrid(MP / 64, NP / 64);
    build_K<<<bgrid, 256>>>(x, y);

    for (int it = 0; it < MAX_ITER; ++it) {
        // a-pass: partials of K @ b (b read directly from g_b)
        sink_matvec<<<(NP / RPB) * CS, 256>>>((const __half*)k1p,
                                              (const float*)bp, nullptr,
                                              nullptr, (float*)pap);
        // b-pass: partials of K^T @ a (a combined on the fly from g_pa)
        sink_matvec<<<(MP / RPB) * CS, 256>>>((const __half*)k2p, nullptr,
                                              (const float*)pap, p,
                                              (float*)pbp);
        sink_update<<<1, 256>>>(q);
    }

    combine_a<<<NP / 256, 256>>>(p);

    const long long total = (long long)NP * MP;
    if ((long long)out_size == total + 1) {
        finalize_T<<<16384, 256>>>(out + 1, 1);
        reduce_cost<<<1, 256>>>(out);
    } else if ((long long)out_size == total) {
        finalize_T<<<16384, 256>>>(out, 1);
    } else if ((long long)out_size > total) {
        finalize_T<<<16384, 256>>>(out + (out_size - total), 1);
        reduce_cost<<<1, 256>>>(out);
    } else {
        finalize_T<<<16384, 256>>>(nullptr, 0);
        reduce_cost<<<1, 256>>>(out);
    }
}

// round 4
// speedup vs baseline: 1.5723x; 1.3251x over previous
#include <cuda_runtime.h>
#include <cuda_fp16.h>
#include <cuda_fp8.h>
#include <math.h>
#include <stdint.h>

#define NP 8192
#define MP 8192
#define DIMS 32
#define EPSV 10.0f
#define THRESH2 (1e-5f * 1e-5f)
#define MAX_ITER 50
#define FP8_ITERS 38 /* then 12 fp16 polish iterations */
#define SCALE_F 65536.0f
#define INV_SCALE_F (1.0f / 65536.0f)
#define LOG_SCALE_F 11.090354888959125f /* ln(65536) */
#define S8_F 256.0f
#define CS 16
#define CHUNK (MP / CS) /* 512 */
#define RPB 32

// fp16 K (scaled 2^16) row-major + transposed (finalize + polish matvecs);
// fp8 K (scaled 2^8) row-major + transposed (fast matvecs). 384MB scratch.
__device__ __half   g_K1[(size_t)NP * MP];
__device__ __half   g_K1T[(size_t)NP * MP];
__device__ uint8_t  g_K8[(size_t)NP * MP];
__device__ uint8_t  g_K8T[(size_t)NP * MP];
__device__ float g_a[NP];
__device__ float g_b[MP];
__device__ float g_pa[CS * NP]; // partials of K @ b    (layout [cs][row])
__device__ float g_pb[CS * MP]; // partials of K^T @ a  (layout [cs][row])
__device__ float g_errp[32];
__device__ int   g_done;
__device__ float g_part[16384];

// ---------------------------------------------------------------------------
__global__ void sink_init()
{
    int i = blockIdx.x * 256 + threadIdx.x;
    if (i < MP) g_b[i] = 1.0f;
    if (i == 0) g_done = 0;
}

// ---------------------------------------------------------------------------
// Build: e = exp(-max(C,0)/EPS). Store e*2^16 as fp16 (K1 + K1T) and e*2^8
// as fp8 e4m3 (K8 + K8T). 64x64 tile per block.
__global__ __launch_bounds__(256) void build_K(const float* __restrict__ x,
                                               const float* __restrict__ y)
{
    __shared__ float sx[64][DIMS + 1];
    __shared__ float sy[64][DIMS + 1];
    __shared__ float sx2[64];
    __shared__ float sy2[64];
    __shared__ __half  stile[64][65];
    __shared__ uint8_t s8tile[64][68];

    const int tid = threadIdx.x;
    const int I0 = blockIdx.y * 64;
    const int J0 = blockIdx.x * 64;

    for (int idx = tid; idx < 64 * DIMS; idx += 256) {
        int r = idx >> 5, k = idx & 31;
        sx[r][k] = x[(I0 + r) * DIMS + k];
        sy[r][k] = y[(J0 + r) * DIMS + k];
    }
    __syncthreads();
    if (tid < 64) {
        float s = 0.f;
        #pragma unroll
        for (int k = 0; k < DIMS; k++) { float v = sx[tid][k]; s = fmaf(v, v, s); }
        sx2[tid] = s;
    } else if (tid < 128) {
        int r = tid - 64;
        float s = 0.f;
        #pragma unroll
        for (int k = 0; k < DIMS; k++) { float v = sy[r][k]; s = fmaf(v, v, s); }
        sy2[r] = s;
    }
    __syncthreads();

    const int ty = tid >> 4, tx = tid & 15;
    const int r0 = ty * 4, c0 = tx * 4;
    float acc[4][4];
    #pragma unroll
    for (int i = 0; i < 4; i++)
        #pragma unroll
        for (int j = 0; j < 4; j++) acc[i][j] = 0.f;

    #pragma unroll
    for (int k = 0; k < DIMS; k++) {
        float a0 = sx[r0 + 0][k], a1 = sx[r0 + 1][k];
        float a2 = sx[r0 + 2][k], a3 = sx[r0 + 3][k];
        float b0 = sy[c0 + 0][k], b1 = sy[c0 + 1][k];
        float b2 = sy[c0 + 2][k], b3 = sy[c0 + 3][k];
        acc[0][0] = fmaf(a0, b0, acc[0][0]); acc[0][1] = fmaf(a0, b1, acc[0][1]);
        acc[0][2] = fmaf(a0, b2, acc[0][2]); acc[0][3] = fmaf(a0, b3, acc[0][3]);
        acc[1][0] = fmaf(a1, b0, acc[1][0]); acc[1][1] = fmaf(a1, b1, acc[1][1]);
        acc[1][2] = fmaf(a1, b2, acc[1][2]); acc[1][3] = fmaf(a1, b3, acc[1][3]);
        acc[2][0] = fmaf(a2, b0, acc[2][0]); acc[2][1] = fmaf(a2, b1, acc[2][1]);
        acc[2][2] = fmaf(a2, b2, acc[2][2]); acc[2][3] = fmaf(a2, b3, acc[2][3]);
        acc[3][0] = fmaf(a3, b0, acc[3][0]); acc[3][1] = fmaf(a3, b1, acc[3][1]);
        acc[3][2] = fmaf(a3, b2, acc[3][2]); acc[3][3] = fmaf(a3, b3, acc[3][3]);
    }

    #pragma unroll
    for (int i = 0; i < 4; i++) {
        #pragma unroll
        for (int j = 0; j < 4; j++) {
            float C = sx2[r0 + i] + sy2[c0 + j] - 2.f * acc[i][j];
            C = fmaxf(C, 0.f);
            float e16 = exp2f(fmaf(C, -0.14426950408889634f, 16.0f));
            stile[r0 + i][c0 + j] = __float2half_rn(fminf(e16, 65504.f));
            s8tile[r0 + i][c0 + j] = (uint8_t)__nv_cvt_float_to_fp8(
                e16 * 0.00390625f, __NV_SATFINITE, __NV_E4M3);
        }
    }
    __syncthreads();

    for (int idx = tid; idx < 4096; idx += 256) {
        int r = idx >> 6, c = idx & 63;
        g_K1[(size_t)(I0 + r) * MP + (J0 + c)] = stile[r][c];
        g_K1T[(size_t)(J0 + r) * NP + (I0 + c)] = stile[c][r];
    }
    for (int idx = tid; idx < 1024; idx += 256) {
        int r = idx >> 4, c4 = (idx & 15) * 4;
        uchar4 v;
        v.x = s8tile[r][c4 + 0]; v.y = s8tile[r][c4 + 1];
        v.z = s8tile[r][c4 + 2]; v.w = s8tile[r][c4 + 3];
        *(uchar4*)(g_K8 + (size_t)(I0 + r) * MP + (J0 + c4)) = v;
        uchar4 t;
        t.x = s8tile[c4 + 0][r]; t.y = s8tile[c4 + 1][r];
        t.z = s8tile[c4 + 2][r]; t.w = s8tile[c4 + 3][r];
        *(uchar4*)(g_K8T + (size_t)(J0 + r) * NP + (I0 + c4)) = t;
    }
}

// ---------------------------------------------------------------------------
// fp8 GEMV partial. Tile = 32 rows x 512 cols per block (16KB of K).
#define W_FMA(wrd, bf4, acc)                                                   \
    {                                                                          \
        __half2_raw lo_ = __nv_cvt_fp8x2_to_halfraw2(                          \
            (__nv_fp8x2_storage_t)((wrd) & 0xffffu), __NV_E4M3);               \
        __half2_raw hi_ = __nv_cvt_fp8x2_to_halfraw2(                          \
            (__nv_fp8x2_storage_t)((wrd) >> 16), __NV_E4M3);                   \
        float2 fl_ = __half22float2(*(__half2*)&lo_);                          \
        float2 fh_ = __half22float2(*(__half2*)&hi_);                          \
        acc = fmaf(fl_.x, (bf4).x, acc); acc = fmaf(fl_.y, (bf4).y, acc);      \
        acc = fmaf(fh_.x, (bf4).z, acc); acc = fmaf(fh_.y, (bf4).w, acc);      \
    }

#define ROW16(v, acc)                                                          \
    { W_FMA((v).x, b0, acc); W_FMA((v).y, b1, acc);                            \
      W_FMA((v).z, b2, acc); W_FMA((v).w, b3, acc); }

__global__ __launch_bounds__(256) void sink_matvec8(
    const uint8_t* __restrict__ K8, const float* __restrict__ vin,
    float* __restrict__ part_out)
{
    if (g_done) return;
    const int cs = blockIdx.x & (CS - 1);
    const int rb = blockIdx.x / CS;
    const int warp = threadIdx.x >> 5;
    const int lane = threadIdx.x & 31;
    const int rbase = rb * RPB + warp * 4;
    const int col0 = cs * CHUNK + lane * 16;

    const float4* bv = (const float4*)(vin + col0);
    float4 b0 = bv[0], b1 = bv[1], b2 = bv[2], b3 = bv[3];

    const size_t base = (size_t)rbase * MP + col0;
    uint4 v0 = __ldcg((const uint4*)(K8 + base));
    uint4 v1 = __ldcg((const uint4*)(K8 + base + MP));
    uint4 v2 = __ldcg((const uint4*)(K8 + base + 2 * MP));
    uint4 v3 = __ldcg((const uint4*)(K8 + base + 3 * MP));

    float a0 = 0.f, a1 = 0.f, a2 = 0.f, a3 = 0.f;
    ROW16(v0, a0);
    ROW16(v1, a1);
    ROW16(v2, a2);
    ROW16(v3, a3);

    #pragma unroll
    for (int o = 16; o; o >>= 1) {
        a0 += __shfl_xor_sync(0xffffffffu, a0, o);
        a1 += __shfl_xor_sync(0xffffffffu, a1, o);
        a2 += __shfl_xor_sync(0xffffffffu, a2, o);
        a3 += __shfl_xor_sync(0xffffffffu, a3, o);
    }
    if (lane == 0)
        *(float4*)(part_out + (size_t)cs * NP + rbase) =
            make_float4(a0, a1, a2, a3);
}

// ---------------------------------------------------------------------------
// fp16 GEMV partial (polish). Same tiling; 2 LDG.128 per row per lane.
#define HQ_FMA(u, bA, bB, acc)                                                 \
    {                                                                          \
        float2 f0_ = __half22float2(*reinterpret_cast<__half2*>(&(u).x));      \
        float2 f1_ = __half22float2(*reinterpret_cast<__half2*>(&(u).y));      \
        float2 f2_ = __half22float2(*reinterpret_cast<__half2*>(&(u).z));      \
        float2 f3_ = __half22float2(*reinterpret_cast<__half2*>(&(u).w));      \
        acc = fmaf(f0_.x, (bA).x, acc); acc = fmaf(f0_.y, (bA).y, acc);        \
        acc = fmaf(f1_.x, (bA).z, acc); acc = fmaf(f1_.y, (bA).w, acc);        \
        acc = fmaf(f2_.x, (bB).x, acc); acc = fmaf(f2_.y, (bB).y, acc);        \
        acc = fmaf(f3_.x, (bB).z, acc); acc = fmaf(f3_.y, (bB).w, acc);        \
    }

__global__ __launch_bounds__(256) void sink_matvec16(
    const __half* __restrict__ K, const float* __restrict__ vin,
    float* __restrict__ part_out)
{
    if (g_done) return;
    const int cs = blockIdx.x & (CS - 1);
    const int rb = blockIdx.x / CS;
    const int warp = threadIdx.x >> 5;
    const int lane = threadIdx.x & 31;
    const int rbase = rb * RPB + warp * 4;
    const int col0 = cs * CHUNK + lane * 16;

    const float4* bv = (const float4*)(vin + col0);
    float4 b0 = bv[0], b1 = bv[1], b2 = bv[2], b3 = bv[3];

    const __half* kr = K + (size_t)rbase * MP + col0;
    float a0 = 0.f, a1 = 0.f, a2 = 0.f, a3 = 0.f;
    {
        uint4 u0 = __ldcg((const uint4*)kr);
        uint4 u1 = __ldcg((const uint4*)kr + 1);
        HQ_FMA(u0, b0, b1, a0); HQ_FMA(u1, b2, b3, a0);
    }
    {
        uint4 u0 = __ldcg((const uint4*)(kr + MP));
        uint4 u1 = __ldcg((const uint4*)(kr + MP) + 1);
        HQ_FMA(u0, b0, b1, a1); HQ_FMA(u1, b2, b3, a1);
    }
    {
        uint4 u0 = __ldcg((const uint4*)(kr + 2 * MP));
        uint4 u1 = __ldcg((const uint4*)(kr + 2 * MP) + 1);
        HQ_FMA(u0, b0, b1, a2); HQ_FMA(u1, b2, b3, a2);
    }
    {
        uint4 u0 = __ldcg((const uint4*)(kr + 3 * MP));
        uint4 u1 = __ldcg((const uint4*)(kr + 3 * MP) + 1);
        HQ_FMA(u0, b0, b1, a3); HQ_FMA(u1, b2, b3, a3);
    }

    #pragma unroll
    for (int o = 16; o; o >>= 1) {
        a0 += __shfl_xor_sync(0xffffffffu, a0, o);
        a1 += __shfl_xor_sync(0xffffffffu, a1, o);
        a2 += __shfl_xor_sync(0xffffffffu, a2, o);
        a3 += __shfl_xor_sync(0xffffffffu, a3, o);
    }
    if (lane == 0)
        *(float4*)(part_out + (size_t)cs * NP + rbase) =
            make_float4(a0, a1, a2, a3);
}

// ---------------------------------------------------------------------------
__global__ __launch_bounds__(256) void sink_combine_a(const float* __restrict__ p,
                                                      float scale)
{
    if (g_done) return;
    const int i = blockIdx.x * 256 + threadIdx.x;
    float s = 0.f;
    #pragma unroll
    for (int c = 0; c < CS; c++) s += g_pa[c * NP + i];
    g_a[i] = __fdividef(p[i] * scale, s);
}

__global__ __launch_bounds__(256) void sink_combine_b(const float* __restrict__ q,
                                                      float scale)
{
    if (g_done) return;
    const int i = blockIdx.x * 256 + threadIdx.x;
    float s = 0.f;
    #pragma unroll
    for (int c = 0; c < CS; c++) s += g_pb[c * MP + i];
    float bn = __fdividef(q[i] * scale, s);
    float d = bn - g_b[i];
    g_b[i] = bn;

    __shared__ float sd[256];
    sd[threadIdx.x] = d * d;
    __syncthreads();
    for (int o = 128; o; o >>= 1) {
        if (threadIdx.x < o) sd[threadIdx.x] += sd[threadIdx.x + o];
        __syncthreads();
    }
    if (threadIdx.x == 0) g_errp[blockIdx.x] = sd[0];
}

__global__ void sink_errcheck()
{
    if (g_done) return;
    if (threadIdx.x == 0) {
        float s = 0.f;
        #pragma unroll
        for (int i = 0; i < 32; i++) s += g_errp[i];
        if (s < THRESH2) g_done = 1;
    }
}

// ---------------------------------------------------------------------------
// T = a * (K1/2^16) * b; cost term = T * C with C = EPS*(ln 2^16 - ln K1).
__global__ __launch_bounds__(256) void finalize_T(float* __restrict__ Tout,
                                                  int write_T)
{
    const size_t e0 = ((size_t)blockIdx.x * 4096) + (size_t)threadIdx.x * 16;
    const int i = (int)(e0 >> 13);
    const float ai = g_a[i] * INV_SCALE_F;
    float cs = 0.f;

    #pragma unroll
    for (int g = 0; g < 4; ++g) {
        const size_t e = e0 + g * 4;
        const int j = (int)(e & 8191);
        uint2 kv2 = *reinterpret_cast<const uint2*>(g_K1 + e);
        __half2 h0 = *reinterpret_cast<__half2*>(&kv2.x);
        __half2 h1 = *reinterpret_cast<__half2*>(&kv2.y);
        float2 f0 = __half22float2(h0);
        float2 f1 = __half22float2(h1);
        const float4 bv = *reinterpret_cast<const float4*>(g_b + j);

        float t0 = ai * f0.x * bv.x;
        float t1 = ai * f0.y * bv.y;
        float t2 = ai * f1.x * bv.z;
        float t3 = ai * f1.y * bv.w;

        if (f0.x > 0.f) cs = fmaf(t0, EPSV * (LOG_SCALE_F - __logf(f0.x)), cs);
        if (f0.y > 0.f) cs = fmaf(t1, EPSV * (LOG_SCALE_F - __logf(f0.y)), cs);
        if (f1.x > 0.f) cs = fmaf(t2, EPSV * (LOG_SCALE_F - __logf(f1.x)), cs);
        if (f1.y > 0.f) cs = fmaf(t3, EPSV * (LOG_SCALE_F - __logf(f1.y)), cs);

        if (write_T) {
            if ((((uintptr_t)Tout) & 15) == 0) {
                *reinterpret_cast<float4*>(Tout + e) = make_float4(t0, t1, t2, t3);
            } else {
                Tout[e + 0] = t0;
                Tout[e + 1] = t1;
                Tout[e + 2] = t2;
                Tout[e + 3] = t3;
            }
        }
    }

    __shared__ float sd[256];
    sd[threadIdx.x] = cs;
    __syncthreads();
    for (int o = 128; o; o >>= 1) {
        if (threadIdx.x < o) sd[threadIdx.x] += sd[threadIdx.x + o];
        __syncthreads();
    }
    if (threadIdx.x == 0) g_part[blockIdx.x] = sd[0];
}

__global__ __launch_bounds__(256) void reduce_cost(float* __restrict__ cost_out)
{
    __shared__ double sd[256];
    double s = 0.0;
    for (int i = threadIdx.x; i < 16384; i += 256) s += (double)g_part[i];
    sd[threadIdx.x] = s;
    __syncthreads();
    for (int o = 128; o; o >>= 1) {
        if (threadIdx.x < o) sd[threadIdx.x] += sd[threadIdx.x + o];
        __syncthreads();
    }
    if (threadIdx.x == 0) cost_out[0] = (float)sd[0];
}

// ---------------------------------------------------------------------------
extern "C" void kernel_launch(void* const* d_in, const int* in_sizes, int n_in,
                              void* d_out, int out_size)
{
    const float* x = (const float*)d_in[0];
    const float* y = (const float*)d_in[1];
    const float* p = (const float*)d_in[2];
    const float* q = (const float*)d_in[3];
    float* out = (float*)d_out;

    void *k1p, *k1tp, *k8p, *k8tp, *ap, *bp, *pap, *pbp;
    cudaGetSymbolAddress(&k1p, g_K1);
    cudaGetSymbolAddress(&k1tp, g_K1T);
    cudaGetSymbolAddress(&k8p, g_K8);
    cudaGetSymbolAddress(&k8tp, g_K8T);
    cudaGetSymbolAddress(&ap, g_a);
    cudaGetSymbolAddress(&bp, g_b);
    cudaGetSymbolAddress(&pap, g_pa);
    cudaGetSymbolAddress(&pbp, g_pb);

    sink_init<<<32, 256>>>();
    dim3 bgrid(MP / 64, NP / 64);
    build_K<<<bgrid, 256>>>(x, y);

    const int mv_grid = (NP / RPB) * CS; // 4096
    for (int it = 0; it < MAX_ITER; ++it) {
        if (it < FP8_ITERS) {
            sink_matvec8<<<mv_grid, 256>>>((const uint8_t*)k8p,
                                           (const float*)bp, (float*)pap);
            sink_combine_a<<<NP / 256, 256>>>(p, S8_F);
            sink_matvec8<<<mv_grid, 256>>>((const uint8_t*)k8tp,
                                           (const float*)ap, (float*)pbp);
            sink_combine_b<<<MP / 256, 256>>>(q, S8_F);
        } else {
            sink_matvec16<<<mv_grid, 256>>>((const __half*)k1p,
                                            (const float*)bp, (float*)pap);
            sink_combine_a<<<NP / 256, 256>>>(p, SCALE_F);
            sink_matvec16<<<mv_grid, 256>>>((const __half*)k1tp,
                                            (const float*)ap, (float*)pbp);
            sink_combine_b<<<MP / 256, 256>>>(q, SCALE_F);
        }
        sink_errcheck<<<1, 32>>>();
    }

    const long long total = (long long)NP * MP;
    if ((long long)out_size == total + 1) {
        finalize_T<<<16384, 256>>>(out + 1, 1);
        reduce_cost<<<1, 256>>>(out);
    } else if ((long long)out_size == total) {
        finalize_T<<<16384, 256>>>(out, 1);
    } else if ((long long)out_size > total) {
        finalize_T<<<16384, 256>>>(out + (out_size - total), 1);
        reduce_cost<<<1, 256>>>(out);
    } else {
        finalize_T<<<16384, 256>>>(nullptr, 0);
        reduce_cost<<<1, 256>>>(out);
    }
}